// round 5
// baseline (speedup 1.0000x reference)
#include <cuda_runtime.h>

#define MAX_NODES  75008
#define MAX_EDGES  1200128
#define F  64
#define F4 (F / 4)
#define SCAN_B 1024
#define MAX_SCAN_BLOCKS 256

// __device__ scratch (allocation-free rule)
__device__ int   g_offset[MAX_NODES];     // CSR start per node
__device__ int   g_cursor[MAX_NODES];     // atomic fill cursor
__device__ float g_inv[MAX_NODES];        // rsqrt(degree)
__device__ int   g_blocksum[MAX_SCAN_BLOCKS];
__device__ int   g_sorted[MAX_EDGES];     // src ids bucketed by dst
__device__ float g_agg[MAX_NODES * F];

// count[n] = round(degree[n]) - 1  (degree = indeg + 1, free histogram)
__device__ __forceinline__ int node_count(const float* degree, int i, int N) {
    return (i < N) ? (__float2int_rn(degree[i]) - 1) : 0;
}

__device__ __forceinline__ int warp_incl_scan(int v) {
    #pragma unroll
    for (int o = 1; o < 32; o <<= 1) {
        int u = __shfl_up_sync(0xffffffffu, v, o);
        if ((threadIdx.x & 31) >= o) v += u;
    }
    return v;
}

// scan pass 1: per-block sums of counts
__global__ void scan1_kernel(const float* __restrict__ degree, int N) {
    int i = blockIdx.x * SCAN_B + threadIdx.x;
    int c = node_count(degree, i, N);
    int w = __reduce_add_sync(0xffffffffu, c);
    __shared__ int ws[32];
    if ((threadIdx.x & 31) == 0) ws[threadIdx.x >> 5] = w;
    __syncthreads();
    if (threadIdx.x < 32) {
        int v = (threadIdx.x < (SCAN_B / 32)) ? ws[threadIdx.x] : 0;
        v = __reduce_add_sync(0xffffffffu, v);
        if (threadIdx.x == 0) g_blocksum[blockIdx.x] = v;
    }
}

// scan pass 2: exclusive scan of block sums (single block)
__global__ void scan2_kernel(int nb) {
    __shared__ int s[MAX_SCAN_BLOCKS];
    int tid = threadIdx.x;
    int v = (tid < nb) ? g_blocksum[tid] : 0;
    s[tid] = v;
    __syncthreads();
    #pragma unroll
    for (int o = 1; o < MAX_SCAN_BLOCKS; o <<= 1) {
        int u = (tid >= o) ? s[tid - o] : 0;
        __syncthreads();
        s[tid] += u;
        __syncthreads();
    }
    if (tid < nb) g_blocksum[tid] = s[tid] - v;   // exclusive
}

// scan pass 3: offsets + cursors + rsqrt(degree) precompute
__global__ void scan3_kernel(const float* __restrict__ degree, int N) {
    int tid = threadIdx.x;
    int i = blockIdx.x * SCAN_B + tid;
    int c = node_count(degree, i, N);

    int lane = tid & 31, wid = tid >> 5;
    int incl = warp_incl_scan(c);
    __shared__ int ws[32];
    if (lane == 31) ws[wid] = incl;
    __syncthreads();
    if (wid == 0) {
        int v = (lane < (SCAN_B / 32)) ? ws[lane] : 0;
        v = warp_incl_scan(v);
        ws[lane] = v;
    }
    __syncthreads();
    int base = (wid ? ws[wid - 1] : 0) + g_blocksum[blockIdx.x];
    int excl = base + incl - c;
    if (i < N) {
        g_offset[i] = excl;
        g_cursor[i] = excl;
        g_inv[i]    = rsqrtf(degree[i]);
    }
}

// bucket edges by dst. ILP=4: int4 loads, 4 independent atomics + stores
// in flight per thread (bucket was latency-bound at issue=4.5%).
__global__ void bucket_kernel(const int* __restrict__ src,
                              const int* __restrict__ dst, int E) {
    int i = blockIdx.x * blockDim.x + threadIdx.x;
    int E4 = E >> 2;
    if (i < E4) {
        int4 s = __ldg(reinterpret_cast<const int4*>(src) + i);
        int4 d = __ldg(reinterpret_cast<const int4*>(dst) + i);
        int p0 = atomicAdd(&g_cursor[d.x], 1);
        int p1 = atomicAdd(&g_cursor[d.y], 1);
        int p2 = atomicAdd(&g_cursor[d.z], 1);
        int p3 = atomicAdd(&g_cursor[d.w], 1);
        g_sorted[p0] = s.x;
        g_sorted[p1] = s.y;
        g_sorted[p2] = s.z;
        g_sorted[p3] = s.w;
    } else if (i == E4) {                 // tail (E % 4 edges)
        for (int e = E4 * 4; e < E; e++) {
            int pos = atomicAdd(&g_cursor[__ldg(dst + e)], 1);
            g_sorted[pos] = __ldg(src + e);
        }
    }
}

// gather: half-warp per node, lane owns one float4 chunk; register
// accumulation, plain store. Scale via precomputed g_inv (no MUFU in loop).
__global__ void __launch_bounds__(256)
gather_kernel(const float* __restrict__ feature,
              const float* __restrict__ degree, int N) {
    int t = blockIdx.x * blockDim.x + threadIdx.x;
    int node = t >> 4;
    int c = t & 15;
    if (node >= N) return;

    int start = g_offset[node];
    int cnt = __float2int_rn(__ldg(degree + node)) - 1;

    float4 acc = make_float4(0.f, 0.f, 0.f, 0.f);
    const float4* feat4 = reinterpret_cast<const float4*>(feature);

    #pragma unroll 4
    for (int i = 0; i < cnt; i++) {
        int s = __ldg(g_sorted + start + i);      // broadcast across half-warp
        float sc = __ldg(g_inv + s);              // broadcast, L1-resident
        float4 v = __ldg(feat4 + s * F4 + c);
        acc.x = fmaf(sc, v.x, acc.x);
        acc.y = fmaf(sc, v.y, acc.y);
        acc.z = fmaf(sc, v.z, acc.z);
        acc.w = fmaf(sc, v.w, acc.w);
    }
    reinterpret_cast<float4*>(g_agg)[node * F4 + c] = acc;  // covers cnt==0
}

// node apply: out[n] = (agg[n] * g_inv[n]) @ W + b. FFMA-roofline.
__global__ void __launch_bounds__(256)
gemm_kernel(const float* __restrict__ W,
            const float* __restrict__ b,
            float* __restrict__ out, int N) {
    __shared__ float4 Ws[F * F4];
    __shared__ float4 bs[F4];

    for (int i = threadIdx.x; i < F * F4; i += blockDim.x)
        Ws[i] = reinterpret_cast<const float4*>(W)[i];
    if (threadIdx.x < F4)
        bs[threadIdx.x] = reinterpret_cast<const float4*>(b)[threadIdx.x];
    __syncthreads();

    int row = blockIdx.x * blockDim.x + threadIdx.x;
    if (row >= N) return;

    float acc[F];
    #pragma unroll
    for (int j = 0; j < F4; j++) {
        float4 bb = bs[j];
        acc[4 * j + 0] = bb.x; acc[4 * j + 1] = bb.y;
        acc[4 * j + 2] = bb.z; acc[4 * j + 3] = bb.w;
    }

    float s = g_inv[row];
    const float4* arow = reinterpret_cast<const float4*>(g_agg + (long)row * F);

    #pragma unroll 4
    for (int k4 = 0; k4 < F4; k4++) {
        float4 hv = __ldg(arow + k4);
        hv.x *= s; hv.y *= s; hv.z *= s; hv.w *= s;
        #pragma unroll
        for (int kk = 0; kk < 4; kk++) {
            float h = (kk == 0) ? hv.x : (kk == 1) ? hv.y : (kk == 2) ? hv.z : hv.w;
            int k = k4 * 4 + kk;
            #pragma unroll
            for (int j = 0; j < F4; j++) {
                float4 w = Ws[k * F4 + j];      // warp-uniform smem broadcast
                acc[4 * j + 0] += h * w.x;
                acc[4 * j + 1] += h * w.y;
                acc[4 * j + 2] += h * w.z;
                acc[4 * j + 3] += h * w.w;
            }
        }
    }

    float4* orow = reinterpret_cast<float4*>(out + (long)row * F);
    #pragma unroll
    for (int j = 0; j < F4; j++)
        orow[j] = make_float4(acc[4 * j + 0], acc[4 * j + 1],
                              acc[4 * j + 2], acc[4 * j + 3]);
}

// ---------------------------------------------------------------------------
extern "C" void kernel_launch(void* const* d_in, const int* in_sizes, int n_in,
                              void* d_out, int out_size) {
    const float* feature = (const float*)d_in[0];
    const float* degree  = (const float*)d_in[1];
    const int*   src     = (const int*)d_in[2];
    const int*   dst     = (const int*)d_in[3];
    const float* W       = (const float*)d_in[4];
    const float* b       = (const float*)d_in[5];
    float*       out     = (float*)d_out;

    int N = in_sizes[1];
    int E = in_sizes[2];
    int nb = (N + SCAN_B - 1) / SCAN_B;

    scan1_kernel<<<nb, SCAN_B>>>(degree, N);
    scan2_kernel<<<1, MAX_SCAN_BLOCKS>>>(nb);
    scan3_kernel<<<nb, SCAN_B>>>(degree, N);

    int bthreads = (E >> 2) + 1;          // ILP=4 + tail thread
    bucket_kernel<<<(bthreads + 255) / 256, 256>>>(src, dst, E);

    int gthreads = N * 16;
    gather_kernel<<<(gthreads + 255) / 256, 256>>>(feature, degree, N);

    gemm_kernel<<<(N + 255) / 256, 256>>>(W, b, out, N);
}

// round 6
// speedup vs baseline: 1.0531x; 1.0531x over previous
#include <cuda_runtime.h>
#include <cuda_fp16.h>

#define MAX_NODES  75008
#define MAX_EDGES  1200128
#define F  64
#define F4 (F / 4)
#define SCAN_B 1024
#define MAX_SCAN_BLOCKS 256

// __device__ scratch (allocation-free rule)
__device__ int   g_offset[MAX_NODES];       // CSR start per node
__device__ int   g_cursor[MAX_NODES];       // atomic fill cursor
__device__ float g_inv[MAX_NODES];          // rsqrt(degree)
__device__ int   g_blocksum[MAX_SCAN_BLOCKS];
__device__ int   g_sorted[MAX_EDGES];       // src ids bucketed by dst
__device__ uint4 g_P[MAX_NODES * 8];        // fp16 messages: row = 8 x uint4 = 64 halves
__device__ float g_agg[MAX_NODES * F];

// count[n] = round(degree[n]) - 1  (degree = indeg + 1 -> free histogram)
__device__ __forceinline__ int node_count(const float* degree, int i, int N) {
    return (i < N) ? (__float2int_rn(degree[i]) - 1) : 0;
}

__device__ __forceinline__ int warp_incl_scan(int v) {
    #pragma unroll
    for (int o = 1; o < 32; o <<= 1) {
        int u = __shfl_up_sync(0xffffffffu, v, o);
        if ((threadIdx.x & 31) >= o) v += u;
    }
    return v;
}

// scan pass 1: per-block sums of counts
__global__ void scan1_kernel(const float* __restrict__ degree, int N) {
    int i = blockIdx.x * SCAN_B + threadIdx.x;
    int c = node_count(degree, i, N);
    int w = __reduce_add_sync(0xffffffffu, c);
    __shared__ int ws[32];
    if ((threadIdx.x & 31) == 0) ws[threadIdx.x >> 5] = w;
    __syncthreads();
    if (threadIdx.x < 32) {
        int v = (threadIdx.x < (SCAN_B / 32)) ? ws[threadIdx.x] : 0;
        v = __reduce_add_sync(0xffffffffu, v);
        if (threadIdx.x == 0) g_blocksum[blockIdx.x] = v;
    }
}

// scan pass 2: exclusive scan of block sums (single block)
__global__ void scan2_kernel(int nb) {
    __shared__ int s[MAX_SCAN_BLOCKS];
    int tid = threadIdx.x;
    int v = (tid < nb) ? g_blocksum[tid] : 0;
    s[tid] = v;
    __syncthreads();
    #pragma unroll
    for (int o = 1; o < MAX_SCAN_BLOCKS; o <<= 1) {
        int u = (tid >= o) ? s[tid - o] : 0;
        __syncthreads();
        s[tid] += u;
        __syncthreads();
    }
    if (tid < nb) g_blocksum[tid] = s[tid] - v;   // exclusive
}

// scan pass 3: offsets + cursors + rsqrt(degree)
__global__ void scan3_kernel(const float* __restrict__ degree, int N) {
    int tid = threadIdx.x;
    int i = blockIdx.x * SCAN_B + tid;
    int c = node_count(degree, i, N);

    int lane = tid & 31, wid = tid >> 5;
    int incl = warp_incl_scan(c);
    __shared__ int ws[32];
    if (lane == 31) ws[wid] = incl;
    __syncthreads();
    if (wid == 0) {
        int v = (lane < (SCAN_B / 32)) ? ws[lane] : 0;
        v = warp_incl_scan(v);
        ws[lane] = v;
    }
    __syncthreads();
    int base = (wid ? ws[wid - 1] : 0) + g_blocksum[blockIdx.x];
    int excl = base + incl - c;
    if (i < N) {
        g_offset[i] = excl;
        g_cursor[i] = excl;
        g_inv[i]    = rsqrtf(degree[i]);
    }
}

// prescale: P[n] = fp16(feature[n] * rsqrt(degree[n])). 8 threads per row,
// each converts 8 floats -> 1 uint4 of halves. Streams 29MB, ~3us.
__global__ void prescale_kernel(const float* __restrict__ feature,
                                const float* __restrict__ degree, int N) {
    int t = blockIdx.x * blockDim.x + threadIdx.x;
    int node = t >> 3;
    int c = t & 7;
    if (node >= N) return;

    float s = rsqrtf(__ldg(degree + node));   // broadcast across 8 lanes
    const float4* frow = reinterpret_cast<const float4*>(feature) + node * F4 + c * 2;
    float4 a = __ldg(frow);
    float4 b = __ldg(frow + 1);

    __half2 h0 = __floats2half2_rn(a.x * s, a.y * s);
    __half2 h1 = __floats2half2_rn(a.z * s, a.w * s);
    __half2 h2 = __floats2half2_rn(b.x * s, b.y * s);
    __half2 h3 = __floats2half2_rn(b.z * s, b.w * s);

    uint4 p;
    p.x = *reinterpret_cast<unsigned*>(&h0);
    p.y = *reinterpret_cast<unsigned*>(&h1);
    p.z = *reinterpret_cast<unsigned*>(&h2);
    p.w = *reinterpret_cast<unsigned*>(&h3);
    g_P[node * 8 + c] = p;
}

// bucket edges by dst — scalar version (R4: ILP=4 regressed; wavefront-bound)
__global__ void bucket_kernel(const int* __restrict__ src,
                              const int* __restrict__ dst, int E) {
    int e = blockIdx.x * blockDim.x + threadIdx.x;
    if (e < E) {
        int d = __ldg(dst + e);
        int pos = atomicAdd(&g_cursor[d], 1);
        g_sorted[pos] = __ldg(src + e);
    }
}

// gather: 8 lanes per node, lane owns 8 half columns (one uint4 = 16B).
// Per edge reads 128B (fp16) instead of 256B (fp32) -> halved LTS traffic.
// fp32 accumulation; plain float4 stores.
__global__ void __launch_bounds__(256)
gather_kernel(const float* __restrict__ degree, int N) {
    int t = blockIdx.x * blockDim.x + threadIdx.x;
    int node = t >> 3;
    int c = t & 7;
    if (node >= N) return;

    int start = g_offset[node];
    int cnt = __float2int_rn(__ldg(degree + node)) - 1;

    float acc[8] = {0.f, 0.f, 0.f, 0.f, 0.f, 0.f, 0.f, 0.f};

    #pragma unroll 4
    for (int i = 0; i < cnt; i++) {
        int s = __ldg(g_sorted + start + i);         // broadcast across 8 lanes
        uint4 p = g_P[s * 8 + c];
        __half2 h0 = *reinterpret_cast<__half2*>(&p.x);
        __half2 h1 = *reinterpret_cast<__half2*>(&p.y);
        __half2 h2 = *reinterpret_cast<__half2*>(&p.z);
        __half2 h3 = *reinterpret_cast<__half2*>(&p.w);
        float2 f0 = __half22float2(h0);
        float2 f1 = __half22float2(h1);
        float2 f2 = __half22float2(h2);
        float2 f3 = __half22float2(h3);
        acc[0] += f0.x; acc[1] += f0.y;
        acc[2] += f1.x; acc[3] += f1.y;
        acc[4] += f2.x; acc[5] += f2.y;
        acc[6] += f3.x; acc[7] += f3.y;
    }

    float4* orow = reinterpret_cast<float4*>(g_agg + node * F + c * 8);
    orow[0] = make_float4(acc[0], acc[1], acc[2], acc[3]);
    orow[1] = make_float4(acc[4], acc[5], acc[6], acc[7]);
}

// node apply: out[n] = (agg[n] * g_inv[n]) @ W + b. FFMA-roofline.
__global__ void __launch_bounds__(256)
gemm_kernel(const float* __restrict__ W,
            const float* __restrict__ b,
            float* __restrict__ out, int N) {
    __shared__ float4 Ws[F * F4];
    __shared__ float4 bs[F4];

    for (int i = threadIdx.x; i < F * F4; i += blockDim.x)
        Ws[i] = reinterpret_cast<const float4*>(W)[i];
    if (threadIdx.x < F4)
        bs[threadIdx.x] = reinterpret_cast<const float4*>(b)[threadIdx.x];
    __syncthreads();

    int row = blockIdx.x * blockDim.x + threadIdx.x;
    if (row >= N) return;

    float acc[F];
    #pragma unroll
    for (int j = 0; j < F4; j++) {
        float4 bb = bs[j];
        acc[4 * j + 0] = bb.x; acc[4 * j + 1] = bb.y;
        acc[4 * j + 2] = bb.z; acc[4 * j + 3] = bb.w;
    }

    float s = g_inv[row];
    const float4* arow = reinterpret_cast<const float4*>(g_agg + (long)row * F);

    #pragma unroll 4
    for (int k4 = 0; k4 < F4; k4++) {
        float4 hv = __ldg(arow + k4);
        hv.x *= s; hv.y *= s; hv.z *= s; hv.w *= s;
        #pragma unroll
        for (int kk = 0; kk < 4; kk++) {
            float h = (kk == 0) ? hv.x : (kk == 1) ? hv.y : (kk == 2) ? hv.z : hv.w;
            int k = k4 * 4 + kk;
            #pragma unroll
            for (int j = 0; j < F4; j++) {
                float4 w = Ws[k * F4 + j];       // warp-uniform smem broadcast
                acc[4 * j + 0] += h * w.x;
                acc[4 * j + 1] += h * w.y;
                acc[4 * j + 2] += h * w.z;
                acc[4 * j + 3] += h * w.w;
            }
        }
    }

    float4* orow = reinterpret_cast<float4*>(out + (long)row * F);
    #pragma unroll
    for (int j = 0; j < F4; j++)
        orow[j] = make_float4(acc[4 * j + 0], acc[4 * j + 1],
                              acc[4 * j + 2], acc[4 * j + 3]);
}

// ---------------------------------------------------------------------------
extern "C" void kernel_launch(void* const* d_in, const int* in_sizes, int n_in,
                              void* d_out, int out_size) {
    const float* feature = (const float*)d_in[0];
    const float* degree  = (const float*)d_in[1];
    const int*   src     = (const int*)d_in[2];
    const int*   dst     = (const int*)d_in[3];
    const float* W       = (const float*)d_in[4];
    const float* b       = (const float*)d_in[5];
    float*       out     = (float*)d_out;

    int N = in_sizes[1];
    int E = in_sizes[2];
    int nb = (N + SCAN_B - 1) / SCAN_B;

    scan1_kernel<<<nb, SCAN_B>>>(degree, N);
    scan2_kernel<<<1, MAX_SCAN_BLOCKS>>>(nb);
    scan3_kernel<<<nb, SCAN_B>>>(degree, N);

    int pthreads = N * 8;
    prescale_kernel<<<(pthreads + 255) / 256, 256>>>(feature, degree, N);

    bucket_kernel<<<(E + 255) / 256, 256>>>(src, dst, E);

    int gthreads = N * 8;
    gather_kernel<<<(gthreads + 255) / 256, 256>>>(degree, N);

    gemm_kernel<<<(N + 255) / 256, 256>>>(W, b, out, N);
}